// round 2
// baseline (speedup 1.0000x reference)
#include <cuda_runtime.h>
#include <cstdint>

// Problem constants (fixed shapes)
#define BQ 16
#define DQ 128
#define TQ 4096
#define VQ 1024

// Tiling for the fused distance+argmin kernel
#define TILE_M 128            // t-values per block
#define TILE_N 128            // codebook rows per chunk
#define NCHUNK (VQ / TILE_N)  // 8
#define KK     (DQ / 2)       // 64 packed-k (f32x2) steps
#define XSTRIDE (TILE_M + 2)  // 130 (ull units per kk-row), even -> 16B aligned rows
#define CSTRIDE (TILE_N + 2)  // 130

// SMEM: Xs (KK*XSTRIDE ull) + Cs (KK*CSTRIDE ull) + csq (VQ floats)
#define SMEM_XS_U (KK * XSTRIDE)
#define SMEM_CS_U (KK * CSTRIDE)
#define SMEM_BYTES (SMEM_XS_U * 8 + SMEM_CS_U * 8 + VQ * 4)

__device__ float g_csq[VQ];

// ---------------------------------------------------------------------------
// Kernel 1: c_sq[v] = sum_d codebook[v][d]^2   (one warp per v)
// ---------------------------------------------------------------------------
__global__ void csq_kernel(const float* __restrict__ cb) {
    int w = (blockIdx.x * blockDim.x + threadIdx.x) >> 5;
    int lane = threadIdx.x & 31;
    if (w >= VQ) return;
    const float* row = cb + (size_t)w * DQ;
    float s = 0.f;
#pragma unroll
    for (int i = lane; i < DQ; i += 32) {
        float x = row[i];
        s += x * x;
    }
#pragma unroll
    for (int off = 16; off; off >>= 1)
        s += __shfl_down_sync(0xffffffffu, s, off);
    if (lane == 0) g_csq[w] = s;
}

// ---------------------------------------------------------------------------
// Kernel 2: fused  score[t][v] = csq[v] - 2 * dot(x_t, c_v)  + running argmin
// Block: 256 threads, TILE_M=128 t-values of one batch b, V looped in 8
// chunks of 128 codes. K=128 packed as 64 f32x2 steps. Micro-tile 8x8 per
// thread using fma.rn.f32x2 (packed along K).
// Codes are written as FLOAT values (harness output dtype is float32).
// ---------------------------------------------------------------------------
__global__ void __launch_bounds__(256, 1)
argmin_kernel(const float* __restrict__ latents,
              const float* __restrict__ cb,
              float* __restrict__ codes) {
    extern __shared__ unsigned char smem_raw[];
    unsigned long long* Xs = (unsigned long long*)smem_raw;          // [KK][XSTRIDE]
    unsigned long long* Cs = Xs + SMEM_XS_U;                         // [KK][CSTRIDE]
    float* csq_s = (float*)(Cs + SMEM_CS_U);                         // [VQ]

    const int tid = threadIdx.x;
    const int tx = tid & 15;   // n-direction (16 threads)
    const int ty = tid >> 4;   // m-direction (16 threads)
    const int b = blockIdx.y;
    const int t0 = blockIdx.x * TILE_M;

    // load csq into smem (whole table, 4KB)
    for (int i = tid; i < VQ; i += 256) csq_s[i] = g_csq[i];

    // load X tile: latents[b][d][t0+t] -> Xs packed pairs along d
    {
        const float* xg = latents + (size_t)b * DQ * TQ + t0;
        float* Xf = (float*)Xs;
        for (int idx = tid; idx < DQ * TILE_M; idx += 256) {
            int d = idx >> 7;          // 0..127
            int t = idx & 127;         // coalesced over t
            float v = xg[(size_t)d * TQ + t];
            Xf[(((unsigned)d >> 1) * XSTRIDE + t) * 2 + (d & 1)] = v;
        }
    }
    __syncthreads();

    float bestv[8];
    int besti[8];
#pragma unroll
    for (int i = 0; i < 8; i++) { bestv[i] = 3.4e38f; besti[i] = 0; }

    for (int vc = 0; vc < NCHUNK; vc++) {
        const int v0 = vc * TILE_N;

        // load C chunk: cb[v0+i][d] -> Cs packed pairs along d
        {
            float* Cf = (float*)Cs;
            const float* cg = cb + (size_t)v0 * DQ;
            for (int idx = tid; idx < TILE_N * DQ; idx += 256) {
                int i = idx >> 7;      // code row within chunk
                int d = idx & 127;     // coalesced over d
                float v = cg[(size_t)i * DQ + d];
                Cf[(((unsigned)d >> 1) * CSTRIDE + i) * 2 + (d & 1)] = v;
            }
        }
        __syncthreads();

        unsigned long long acc[8][8];
#pragma unroll
        for (int mi = 0; mi < 8; mi++)
#pragma unroll
            for (int ni = 0; ni < 8; ni++) acc[mi][ni] = 0ull;

#pragma unroll 2
        for (int kk = 0; kk < KK; kk++) {
            unsigned long long x2[8], c2[8];
            const ulonglong2* xp = (const ulonglong2*)(Xs + kk * XSTRIDE + ty * 8);
            const ulonglong2* cp = (const ulonglong2*)(Cs + kk * CSTRIDE + tx * 8);
#pragma unroll
            for (int i = 0; i < 4; i++) {
                ulonglong2 xv = xp[i];
                x2[2 * i] = xv.x; x2[2 * i + 1] = xv.y;
                ulonglong2 cv = cp[i];
                c2[2 * i] = cv.x; c2[2 * i + 1] = cv.y;
            }
#pragma unroll
            for (int mi = 0; mi < 8; mi++)
#pragma unroll
                for (int ni = 0; ni < 8; ni++) {
                    asm("fma.rn.f32x2 %0, %1, %2, %0;"
                        : "+l"(acc[mi][ni])
                        : "l"(x2[mi]), "l"(c2[ni]));
                }
        }

        // epilogue: score = csq[v] - 2*dot, running argmin per m-row
#pragma unroll
        for (int mi = 0; mi < 8; mi++) {
#pragma unroll
            for (int ni = 0; ni < 8; ni++) {
                unsigned long long a = acc[mi][ni];
                float lo = __uint_as_float((unsigned)(a & 0xffffffffull));
                float hi = __uint_as_float((unsigned)(a >> 32));
                float dot = lo + hi;
                int v = v0 + tx * 8 + ni;
                float score = csq_s[v] - 2.0f * dot;
                if (score < bestv[mi]) { bestv[mi] = score; besti[mi] = v; }
            }
        }
        __syncthreads();  // protect Cs before next chunk load
    }

    // reduce argmin across the 16 tx-lanes (within 16-lane shuffle groups)
#pragma unroll
    for (int mi = 0; mi < 8; mi++) {
        float s = bestv[mi];
        int v = besti[mi];
#pragma unroll
        for (int off = 8; off; off >>= 1) {
            float os = __shfl_down_sync(0xffffffffu, s, off, 16);
            int ov = __shfl_down_sync(0xffffffffu, v, off, 16);
            if (os < s || (os == s && ov < v)) { s = os; v = ov; }
        }
        if (tx == 0) codes[(size_t)b * TQ + t0 + ty * 8 + mi] = (float)v;
    }
}

// ---------------------------------------------------------------------------
// Kernel 3: quantized[b][d][t] = codebook[codes[b][t]][d]
// Each thread: 4 consecutive t for a fixed (b,d). float4 stores.
// Codes are stored as float values; convert back to int for indexing.
// ---------------------------------------------------------------------------
__global__ void gather_kernel(const float* __restrict__ cb,
                              const float* __restrict__ codes,
                              float* __restrict__ quant) {
    int idx = blockIdx.x * blockDim.x + threadIdx.x;  // 0 .. B*D*T/4-1
    int t4 = idx & (TQ / 4 - 1);
    int rest = idx >> 10;          // b*D + d
    int d = rest & (DQ - 1);
    int b = rest >> 7;
    const float4 c4 = *(const float4*)(codes + (size_t)b * TQ + t4 * 4);
    int i0 = (int)c4.x;
    int i1 = (int)c4.y;
    int i2 = (int)c4.z;
    int i3 = (int)c4.w;
    float4 o;
    o.x = cb[(size_t)i0 * DQ + d];
    o.y = cb[(size_t)i1 * DQ + d];
    o.z = cb[(size_t)i2 * DQ + d];
    o.w = cb[(size_t)i3 * DQ + d];
    *(float4*)(quant + (size_t)rest * TQ + t4 * 4) = o;
}

// ---------------------------------------------------------------------------
extern "C" void kernel_launch(void* const* d_in, const int* in_sizes, int n_in,
                              void* d_out, int out_size) {
    const float* latents = (const float*)d_in[0];   // (B, D, T) fp32
    const float* codebook = (const float*)d_in[1];  // (V, D)    fp32

    // Output layout (float32 throughout): codes (B*T) then quantized (B*D*T)
    float* codes = (float*)d_out;
    float* quant = (float*)d_out + BQ * TQ;

    cudaFuncSetAttribute(argmin_kernel,
                         cudaFuncAttributeMaxDynamicSharedMemorySize,
                         SMEM_BYTES);

    csq_kernel<<<(VQ * 32 + 255) / 256, 256>>>(codebook);

    dim3 grid(TQ / TILE_M, BQ);  // (32, 16) = 512 blocks
    argmin_kernel<<<grid, 256, SMEM_BYTES>>>(latents, codebook, codes);

    int total4 = BQ * DQ * TQ / 4;  // 2M threads
    gather_kernel<<<total4 / 256, 256>>>(codebook, codes, quant);
}

// round 3
// speedup vs baseline: 1.5976x; 1.5976x over previous
#include <cuda_runtime.h>
#include <cstdint>

// Problem constants (fixed shapes)
#define BQ 16
#define DQ 128
#define TQ 4096
#define VQ 1024

// Tiling for the fused distance+argmin kernel
#define TILE_M 128            // t-values per block
#define TILE_N 128            // codebook rows per chunk
#define NCHUNK (VQ / TILE_N)  // 8
#define KK     (DQ / 2)       // 64 packed-k (f32x2) steps
#define XSTRIDE 130           // ull units per kk-row of X (128 + 2 pad, 16B-aligned rows)
#define CSTRIDE 130           // ull units per kk-row of C (64 chunks + 1 pad chunk)

// SMEM: Xs (KK*XSTRIDE ull) + Cs (KK*CSTRIDE ull) + csq (VQ floats)
#define SMEM_XS_U (KK * XSTRIDE)
#define SMEM_CS_U (KK * CSTRIDE)
#define SMEM_BYTES (SMEM_XS_U * 8 + SMEM_CS_U * 8 + VQ * 4)

__device__ float g_csq[VQ];

// ---------------------------------------------------------------------------
// Kernel 1: c_sq[v] = sum_d codebook[v][d]^2   (one warp per v)
// ---------------------------------------------------------------------------
__global__ void csq_kernel(const float* __restrict__ cb) {
    int w = (blockIdx.x * blockDim.x + threadIdx.x) >> 5;
    int lane = threadIdx.x & 31;
    if (w >= VQ) return;
    const float* row = cb + (size_t)w * DQ;
    float s = 0.f;
#pragma unroll
    for (int i = lane; i < DQ; i += 32) {
        float x = row[i];
        s += x * x;
    }
#pragma unroll
    for (int off = 16; off; off >>= 1)
        s += __shfl_down_sync(0xffffffffu, s, off);
    if (lane == 0) g_csq[w] = s;
}

// ---------------------------------------------------------------------------
// Kernel 2: fused  score[t][v] = csq[v] - 2 * dot(x_t, c_v)  + running argmin
//
// C smem layout (conflict-free): each kk-row is a grid of 16B chunks.
//   chunk p = i*16 + tx   (i = 0..3, tx = 0..15)
//   contents: the f32x2 pairs for n = {tx*8 + 2i, tx*8 + 2i + 1} at this kk.
// Compute reads for fixed i are 16 CONTIGUOUS chunks across tx -> 256B
// contiguous -> zero bank conflicts (2 crossbar phases, the minimum).
// ---------------------------------------------------------------------------
__global__ void __launch_bounds__(256, 1)
argmin_kernel(const float* __restrict__ latents,
              const float* __restrict__ cb,
              float* __restrict__ codes) {
    extern __shared__ unsigned char smem_raw[];
    unsigned long long* Xs = (unsigned long long*)smem_raw;          // [KK][XSTRIDE]
    unsigned long long* Cs = Xs + SMEM_XS_U;                         // [KK][CSTRIDE]
    float* csq_s = (float*)(Cs + SMEM_CS_U);                         // [VQ]

    const int tid = threadIdx.x;
    const int tx = tid & 15;   // n-direction (16 threads)
    const int ty = tid >> 4;   // m-direction (16 threads)
    const int b = blockIdx.y;
    const int t0 = blockIdx.x * TILE_M;

    // load csq into smem (whole table, 4KB)
    for (int i = tid; i < VQ; i += 256) csq_s[i] = g_csq[i];

    // load X tile: latents[b][d][t0+t] -> Xs packed pairs along d
    {
        const float* xg = latents + (size_t)b * DQ * TQ + t0;
        float* Xf = (float*)Xs;
        for (int idx = tid; idx < DQ * TILE_M; idx += 256) {
            int d = idx >> 7;          // 0..127
            int t = idx & 127;         // coalesced over t
            float v = xg[(size_t)d * TQ + t];
            Xf[(((unsigned)d >> 1) * XSTRIDE + t) * 2 + (d & 1)] = v;
        }
    }
    __syncthreads();

    float bestv[8];
    int besti[8];
#pragma unroll
    for (int i = 0; i < 8; i++) { bestv[i] = 3.4e38f; besti[i] = 0; }

    for (int vc = 0; vc < NCHUNK; vc++) {
        const int v0 = vc * TILE_N;

        // load C chunk: cb[v0+n][d] -> chunk-grid layout (see header comment)
        {
            float* Cf = (float*)Cs;
            const float* cg = cb + (size_t)v0 * DQ;
            for (int idx = tid; idx < TILE_N * DQ; idx += 256) {
                int n = idx >> 7;      // code row within chunk
                int d = idx & 127;     // coalesced over d
                float v = cg[(size_t)n * DQ + d];
                int kk = d >> 1, dd = d & 1;
                int j = n & 7;
                int chunk = ((j >> 1) << 4) + (n >> 3);   // i*16 + tx
                int u = kk * CSTRIDE + chunk * 2 + (j & 1);
                Cf[u * 2 + dd] = v;
            }
        }
        __syncthreads();

        unsigned long long acc[8][8];
#pragma unroll
        for (int mi = 0; mi < 8; mi++)
#pragma unroll
            for (int ni = 0; ni < 8; ni++) acc[mi][ni] = 0ull;

#pragma unroll 2
        for (int kk = 0; kk < KK; kk++) {
            unsigned long long x2[8], c2[8];
            const ulonglong2* xp = (const ulonglong2*)(Xs + kk * XSTRIDE + ty * 8);
            const ulonglong2* cp = (const ulonglong2*)(Cs + kk * CSTRIDE) + tx;
#pragma unroll
            for (int i = 0; i < 4; i++) {
                ulonglong2 xv = xp[i];
                x2[2 * i] = xv.x; x2[2 * i + 1] = xv.y;
                ulonglong2 cv = cp[i * 16];   // chunk i*16 + tx
                c2[2 * i] = cv.x; c2[2 * i + 1] = cv.y;
            }
#pragma unroll
            for (int mi = 0; mi < 8; mi++)
#pragma unroll
                for (int ni = 0; ni < 8; ni++) {
                    asm("fma.rn.f32x2 %0, %1, %2, %0;"
                        : "+l"(acc[mi][ni])
                        : "l"(x2[mi]), "l"(c2[ni]));
                }
        }

        // epilogue: score = csq[v] - 2*dot, running argmin per m-row
#pragma unroll
        for (int mi = 0; mi < 8; mi++) {
#pragma unroll
            for (int ni = 0; ni < 8; ni++) {
                unsigned long long a = acc[mi][ni];
                float lo = __uint_as_float((unsigned)(a & 0xffffffffull));
                float hi = __uint_as_float((unsigned)(a >> 32));
                float dot = lo + hi;
                int v = v0 + tx * 8 + ni;
                float score = csq_s[v] - 2.0f * dot;
                if (score < bestv[mi]) { bestv[mi] = score; besti[mi] = v; }
            }
        }
        __syncthreads();  // protect Cs before next chunk load
    }

    // reduce argmin across the 16 tx-lanes (within 16-lane shuffle groups)
#pragma unroll
    for (int mi = 0; mi < 8; mi++) {
        float s = bestv[mi];
        int v = besti[mi];
#pragma unroll
        for (int off = 8; off; off >>= 1) {
            float os = __shfl_down_sync(0xffffffffu, s, off, 16);
            int ov = __shfl_down_sync(0xffffffffu, v, off, 16);
            if (os < s || (os == s && ov < v)) { s = os; v = ov; }
        }
        if (tx == 0) codes[(size_t)b * TQ + t0 + ty * 8 + mi] = (float)v;
    }
}

// ---------------------------------------------------------------------------
// Kernel 3: quantized[b][d][t] = codebook[codes[b][t]][d]
// One thread per (b, t, d4): reads a 16B slice of the code's row (vectorized
// gather), writes 4 scalar floats that are coalesced across the warp (t is
// the fastest-varying lane dimension).
// ---------------------------------------------------------------------------
__global__ void gather_kernel(const float* __restrict__ cb,
                              const float* __restrict__ codes,
                              float* __restrict__ quant) {
    int idx = blockIdx.x * blockDim.x + threadIdx.x;  // 0 .. B*T*(D/4)-1
    int t = idx & (TQ - 1);
    int rest = idx >> 12;
    int d4 = rest & (DQ / 4 - 1);   // 0..31
    int b = rest >> 5;
    int c = (int)codes[(size_t)b * TQ + t];
    float4 v = *(const float4*)(cb + (size_t)c * DQ + d4 * 4);
    float* q = quant + (size_t)b * DQ * TQ + (size_t)(d4 * 4) * TQ + t;
    q[0 * TQ] = v.x;
    q[1 * TQ] = v.y;
    q[2 * TQ] = v.z;
    q[3 * TQ] = v.w;
}

// ---------------------------------------------------------------------------
extern "C" void kernel_launch(void* const* d_in, const int* in_sizes, int n_in,
                              void* d_out, int out_size) {
    const float* latents = (const float*)d_in[0];   // (B, D, T) fp32
    const float* codebook = (const float*)d_in[1];  // (V, D)    fp32

    // Output layout (float32 throughout): codes (B*T) then quantized (B*D*T)
    float* codes = (float*)d_out;
    float* quant = (float*)d_out + BQ * TQ;

    cudaFuncSetAttribute(argmin_kernel,
                         cudaFuncAttributeMaxDynamicSharedMemorySize,
                         SMEM_BYTES);

    csq_kernel<<<(VQ * 32 + 255) / 256, 256>>>(codebook);

    dim3 grid(TQ / TILE_M, BQ);  // (32, 16) = 512 blocks
    argmin_kernel<<<grid, 256, SMEM_BYTES>>>(latents, codebook, codes);

    int total = BQ * TQ * (DQ / 4);  // 2M threads
    gather_kernel<<<total / 256, 256>>>(codebook, codes, quant);
}

// round 5
// speedup vs baseline: 2.2753x; 1.4241x over previous
#include <cuda_runtime.h>
#include <cuda_bf16.h>
#include <cstdint>

// Problem constants
#define BQ 16
#define DQ 128
#define TQ 4096
#define VQ 1024

#define TILE_M 128
#define TILE_N 128
#define NCHUNK (VQ / TILE_N)   // 8

// Dynamic SMEM layout (bytes)
#define OFF_MERGEV 0                    // 2*128 floats
#define OFF_MERGEI 1024                 // 2*128 ints
#define OFF_CSQ    2048                 // 1024 floats
#define OFF_TILES  6144
#define TILE_BYTES 32768                // 128x128 bf16
#define OFF_AH (OFF_TILES + 0 * TILE_BYTES)
#define OFF_AM (OFF_TILES + 1 * TILE_BYTES)
#define OFF_AL (OFF_TILES + 2 * TILE_BYTES)
#define OFF_BH (OFF_TILES + 3 * TILE_BYTES)
#define OFF_BM (OFF_TILES + 4 * TILE_BYTES)
#define OFF_BL (OFF_TILES + 5 * TILE_BYTES)
#define SMEM_TOTAL (OFF_TILES + 6 * TILE_BYTES)   // 202752 B

__device__ float g_csq[VQ];
__device__ __nv_bfloat16 g_ch[VQ * DQ];
__device__ __nv_bfloat16 g_cm[VQ * DQ];
__device__ __nv_bfloat16 g_cl[VQ * DQ];

// ---------------------------------------------------------------------------
__device__ __forceinline__ uint32_t smem_u32(const void* p) {
    uint32_t a;
    asm("{ .reg .u64 t; cvta.to.shared.u64 t, %1; cvt.u32.u64 %0, t; }"
        : "=r"(a) : "l"(p));
    return a;
}

#define LDMX4(r, addr) \
    asm volatile("ldmatrix.sync.aligned.m8n8.x4.shared.b16 {%0,%1,%2,%3}, [%4];" \
        : "=r"((r)[0]), "=r"((r)[1]), "=r"((r)[2]), "=r"((r)[3]) \
        : "r"(addr))

__device__ __forceinline__ void mma_bf16(float* c, const uint32_t* a,
                                         const uint32_t* b) {
    asm volatile(
        "mma.sync.aligned.m16n8k16.row.col.f32.bf16.bf16.f32 "
        "{%0,%1,%2,%3}, {%4,%5,%6,%7}, {%8,%9}, {%0,%1,%2,%3};"
        : "+f"(c[0]), "+f"(c[1]), "+f"(c[2]), "+f"(c[3])
        : "r"(a[0]), "r"(a[1]), "r"(a[2]), "r"(a[3]), "r"(b[0]), "r"(b[1]));
}

// Swizzled byte offset inside a 128x128 bf16 tile (256B rows, 16B chunks,
// chunk column XOR'd with row%8 -> conflict-free ldmatrix over 8 rows).
__device__ __forceinline__ uint32_t tswz(int row, int col2b) {
    // col2b = bf16 column index 0..127
    return (uint32_t)(row * 256 + ((((col2b >> 3) ^ (row & 7)) << 4) |
                                   ((col2b & 7) * 2)));
}

// ---------------------------------------------------------------------------
// Kernel 1: c_sq[v] (fp32)
// ---------------------------------------------------------------------------
__global__ void csq_kernel(const float* __restrict__ cb) {
    int w = (blockIdx.x * blockDim.x + threadIdx.x) >> 5;
    int lane = threadIdx.x & 31;
    if (w >= VQ) return;
    const float* row = cb + (size_t)w * DQ;
    float s = 0.f;
#pragma unroll
    for (int i = lane; i < DQ; i += 32) {
        float x = row[i];
        s += x * x;
    }
#pragma unroll
    for (int off = 16; off; off >>= 1)
        s += __shfl_down_sync(0xffffffffu, s, off);
    if (lane == 0) g_csq[w] = s;
}

// ---------------------------------------------------------------------------
// Kernel 1b: codebook fp32 -> bf16 hi/mid/lo split
// ---------------------------------------------------------------------------
__global__ void cbcvt_kernel(const float* __restrict__ cb) {
    int i = blockIdx.x * blockDim.x + threadIdx.x;
    if (i >= VQ * DQ) return;
    float x = cb[i];
    __nv_bfloat16 h = __float2bfloat16(x);
    float r = x - __bfloat162float(h);
    __nv_bfloat16 m = __float2bfloat16(r);
    float r2 = r - __bfloat162float(m);
    g_ch[i] = h;
    g_cm[i] = m;
    g_cl[i] = __float2bfloat16(r2);
}

// ---------------------------------------------------------------------------
// Kernel 2: HMMA (mma.sync bf16x3) GEMM + fused argmin
// 256 threads = 8 warps in a 4x2 grid; warp tile 32x64; CTA tile 128x128x128.
// 6 products accumulated into one fp32 acc: AhBh, AhBm, AmBh, AmBm, AhBl, AlBh.
// ---------------------------------------------------------------------------
__global__ void __launch_bounds__(256, 1)
vq_kernel(const float* __restrict__ latents, float* __restrict__ codes) {
    extern __shared__ unsigned char sm[];
    const uint32_t smb = smem_u32(sm);
    const int tid = threadIdx.x;
    const int lane = tid & 31;
    const int wid = tid >> 5;
    const int warp_m = wid & 3;    // 0..3  (m32 tiles)
    const int warp_n = wid >> 2;   // 0..1  (n64 tiles)
    const int b = blockIdx.y;
    const int t0 = blockIdx.x * TILE_M;

    float* csq_s = (float*)(sm + OFF_CSQ);
    for (int i = tid; i < VQ; i += 256) csq_s[i] = g_csq[i];

    // A tile: latents[b][d][t0+t] -> split bf16 tiles (row=t, col=d)
    {
        const float* xg = latents + (size_t)b * DQ * TQ + t0;
        for (int idx = tid; idx < DQ * TILE_M; idx += 256) {
            int d = idx >> 7;      // 0..127
            int t = idx & 127;     // coalesced over t
            float x = xg[(size_t)d * TQ + t];
            __nv_bfloat16 h = __float2bfloat16(x);
            float r = x - __bfloat162float(h);
            __nv_bfloat16 m = __float2bfloat16(r);
            float r2 = r - __bfloat162float(m);
            uint32_t o = tswz(t, d);
            *(__nv_bfloat16*)(sm + OFF_AH + o) = h;
            *(__nv_bfloat16*)(sm + OFF_AM + o) = m;
            *(__nv_bfloat16*)(sm + OFF_AL + o) = __float2bfloat16(r2);
        }
    }

    // Per-thread ldmatrix row constants
    const int arow_in16 = lane & 15;
    const int kca = lane >> 4;                        // A k-chunk select
    const int brow_in16 = (lane & 7) | ((lane >> 4) << 3);
    const int kcb = (lane >> 3) & 1;                  // B k-chunk select

    int arow[2], axr[2];
    uint32_t abase[2];
#pragma unroll
    for (int mi = 0; mi < 2; mi++) {
        arow[mi] = warp_m * 32 + mi * 16 + arow_in16;
        axr[mi] = arow[mi] & 7;
        abase[mi] = (uint32_t)(arow[mi] * 256);
    }
    int bxr[4];
    uint32_t bbase[4];
#pragma unroll
    for (int n4 = 0; n4 < 4; n4++) {
        int row = warp_n * 64 + n4 * 16 + brow_in16;
        bxr[n4] = row & 7;
        bbase[n4] = (uint32_t)(row * 256);
    }

    float bestv[4];
    int besti[4];
#pragma unroll
    for (int j = 0; j < 4; j++) { bestv[j] = 3.4e38f; besti[j] = 0; }

    for (int vc = 0; vc < NCHUNK; vc++) {
        const int v0 = vc * TILE_N;
        __syncthreads();   // previous chunk's ldmatrix reads done

        // B chunk: g_c{h,m,l}[v0+n][:] -> swizzled tiles (row=n, col=d)
        {
            const size_t gb = (size_t)v0 * DQ;
            for (int idx = tid; idx < TILE_N * (DQ / 2); idx += 256) {
                int n = idx >> 6;      // 0..127
                int dp = idx & 63;     // bf16 pair index, coalesced
                size_t gi = gb + (size_t)n * DQ + dp * 2;
                uint32_t o = tswz(n, dp * 2);
                *(uint32_t*)(sm + OFF_BH + o) = *(const uint32_t*)(g_ch + gi);
                *(uint32_t*)(sm + OFF_BM + o) = *(const uint32_t*)(g_cm + gi);
                *(uint32_t*)(sm + OFF_BL + o) = *(const uint32_t*)(g_cl + gi);
            }
        }
        __syncthreads();

        float acc[2][8][4];
#pragma unroll
        for (int mi = 0; mi < 2; mi++)
#pragma unroll
            for (int ni = 0; ni < 8; ni++)
#pragma unroll
                for (int q = 0; q < 4; q++) acc[mi][ni][q] = 0.f;

#pragma unroll 2
        for (int ks = 0; ks < 8; ks++) {
            uint32_t aH[2][4], aM[2][4], aL[2][4];
#pragma unroll
            for (int mi = 0; mi < 2; mi++) {
                uint32_t co = (uint32_t)((((ks << 1) | kca) ^ axr[mi]) << 4);
                uint32_t ad = smb + abase[mi] + co;
                LDMX4(aH[mi], ad + OFF_AH);
                LDMX4(aM[mi], ad + OFF_AM);
                LDMX4(aL[mi], ad + OFF_AL);
            }
            uint32_t bH[8][2], bM[8][2], bL[8][2];
#pragma unroll
            for (int n4 = 0; n4 < 4; n4++) {
                uint32_t co = (uint32_t)((((ks << 1) | kcb) ^ bxr[n4]) << 4);
                uint32_t bd = smb + bbase[n4] + co;
                uint32_t r[4];
                LDMX4(r, bd + OFF_BH);
                bH[n4 * 2][0] = r[0]; bH[n4 * 2][1] = r[1];
                bH[n4 * 2 + 1][0] = r[2]; bH[n4 * 2 + 1][1] = r[3];
                LDMX4(r, bd + OFF_BM);
                bM[n4 * 2][0] = r[0]; bM[n4 * 2][1] = r[1];
                bM[n4 * 2 + 1][0] = r[2]; bM[n4 * 2 + 1][1] = r[3];
                LDMX4(r, bd + OFF_BL);
                bL[n4 * 2][0] = r[0]; bL[n4 * 2][1] = r[1];
                bL[n4 * 2 + 1][0] = r[2]; bL[n4 * 2 + 1][1] = r[3];
            }
#pragma unroll
            for (int mi = 0; mi < 2; mi++)
#pragma unroll
                for (int ni = 0; ni < 8; ni++) {
                    float* c = acc[mi][ni];
                    mma_bf16(c, aH[mi], bH[ni]);
                    mma_bf16(c, aH[mi], bM[ni]);
                    mma_bf16(c, aM[mi], bH[ni]);
                    mma_bf16(c, aM[mi], bM[ni]);
                    mma_bf16(c, aH[mi], bL[ni]);
                    mma_bf16(c, aL[mi], bH[ni]);
                }
        }

        // Epilogue: score = csq[v] - 2*dot, running argmin.
        // acc[mi][ni]: c0=(row g, col 2tg) c1=(g,2tg+1) c2=(g+8,2tg) c3=(g+8,2tg+1)
#pragma unroll
        for (int ni = 0; ni < 8; ni++) {
            int col0 = v0 + warp_n * 64 + ni * 8 + (lane & 3) * 2;
            float cs0 = csq_s[col0];
            float cs1 = csq_s[col0 + 1];
#pragma unroll
            for (int mi = 0; mi < 2; mi++) {
                const float* c = acc[mi][ni];
                float s0 = fmaf(-2.f, c[0], cs0);
                float s1 = fmaf(-2.f, c[1], cs1);
                float s2 = fmaf(-2.f, c[2], cs0);
                float s3 = fmaf(-2.f, c[3], cs1);
                int j0 = mi * 2, j1 = mi * 2 + 1;
                if (s0 < bestv[j0]) { bestv[j0] = s0; besti[j0] = col0; }
                if (s1 < bestv[j0]) { bestv[j0] = s1; besti[j0] = col0 + 1; }
                if (s2 < bestv[j1]) { bestv[j1] = s2; besti[j1] = col0; }
                if (s3 < bestv[j1]) { bestv[j1] = s3; besti[j1] = col0 + 1; }
            }
        }
    }

    // Reduce across the 4 lanes sharing each row (lane&3 quad)
#pragma unroll
    for (int j = 0; j < 4; j++) {
        float v = bestv[j];
        int ix = besti[j];
#pragma unroll
        for (int off = 1; off <= 2; off <<= 1) {
            float ov = __shfl_xor_sync(0xffffffffu, v, off);
            int oi = __shfl_xor_sync(0xffffffffu, ix, off);
            if (ov < v || (ov == v && oi < ix)) { v = ov; ix = oi; }
        }
        bestv[j] = v;
        besti[j] = ix;
    }

    // Merge the two warp_n column halves via smem
    float* mv = (float*)(sm + OFF_MERGEV);   // [2][128]
    int* mi_ = (int*)(sm + OFF_MERGEI);      // [2][128]
    __syncthreads();
    if ((lane & 3) == 0) {
#pragma unroll
        for (int j = 0; j < 4; j++) {
            int row = warp_m * 32 + (j >> 1) * 16 + (j & 1) * 8 + (lane >> 2);
            mv[warp_n * 128 + row] = bestv[j];
            mi_[warp_n * 128 + row] = besti[j];
        }
    }
    __syncthreads();
    if (tid < 128) {
        float va = mv[tid];
        int ia = mi_[tid];
        float vb = mv[128 + tid];
        int ib = mi_[128 + tid];
        if (vb < va || (vb == va && ib < ia)) { va = vb; ia = ib; }
        codes[(size_t)b * TQ + t0 + tid] = (float)ia;
    }
}

// ---------------------------------------------------------------------------
// Kernel 3: quantized[b][d][t] = codebook[codes[b][t]][d]
// ---------------------------------------------------------------------------
__global__ void gather_kernel(const float* __restrict__ cb,
                              const float* __restrict__ codes,
                              float* __restrict__ quant) {
    int idx = blockIdx.x * blockDim.x + threadIdx.x;
    int t = idx & (TQ - 1);
    int rest = idx >> 12;
    int d4 = rest & (DQ / 4 - 1);
    int b = rest >> 5;
    int c = (int)codes[(size_t)b * TQ + t];
    float4 v = *(const float4*)(cb + (size_t)c * DQ + d4 * 4);
    float* q = quant + (size_t)b * DQ * TQ + (size_t)(d4 * 4) * TQ + t;
    q[0 * TQ] = v.x;
    q[1 * TQ] = v.y;
    q[2 * TQ] = v.z;
    q[3 * TQ] = v.w;
}

// ---------------------------------------------------------------------------
extern "C" void kernel_launch(void* const* d_in, const int* in_sizes, int n_in,
                              void* d_out, int out_size) {
    const float* latents = (const float*)d_in[0];   // (B, D, T) fp32
    const float* codebook = (const float*)d_in[1];  // (V, D)    fp32

    float* codes = (float*)d_out;             // B*T floats
    float* quant = (float*)d_out + BQ * TQ;   // B*D*T floats

    cudaFuncSetAttribute(vq_kernel,
                         cudaFuncAttributeMaxDynamicSharedMemorySize,
                         SMEM_TOTAL);

    csq_kernel<<<(VQ * 32 + 255) / 256, 256>>>(codebook);
    cbcvt_kernel<<<(VQ * DQ + 255) / 256, 256>>>(codebook);

    dim3 grid(TQ / TILE_M, BQ);   // (32, 16) = 512 blocks
    vq_kernel<<<grid, 256, SMEM_TOTAL>>>(latents, codes);

    int total = BQ * TQ * (DQ / 4);
    gather_kernel<<<total / 256, 256>>>(codebook, codes, quant);
}

// round 6
// speedup vs baseline: 3.1788x; 1.3971x over previous
#include <cuda_runtime.h>
#include <cuda_bf16.h>
#include <cstdint>

// Problem constants
#define BQ 16
#define DQ 128
#define TQ 4096
#define VQ 1024

#define TILE_M 128
#define TILE_N 128
#define NCHUNK 8
#define MARGIN 3.0f
#define QCAP 8192

// Dynamic SMEM layout (bytes)
#define OFF_RES    0          // 128 x u64 packed (score,idx)
#define OFF_ROWMIN 1024       // 128 x u32 (order-uint running cheap min)
#define OFF_QN     1536       // queue counter
#define OFF_CSQ    2048       // 1024 floats
#define OFF_AF     6144       // fp32 A [128][AF_STRIDE]
#define AF_STRIDE  132
#define OFF_AH     73728      // bf16 A tile 32KB (swizzled)
#define OFF_B      106496     // bf16 B tiles, 2 x 32KB (double buffer)
#define BTILE      32768
#define OFF_QUEUE  172032     // QCAP x u32
#define SMEM_TOTAL 204800

__device__ float g_csq[VQ];
__device__ __nv_bfloat16 g_ch[VQ * DQ];

// ---------------------------------------------------------------------------
__device__ __forceinline__ uint32_t smem_u32(const void* p) {
    uint32_t a;
    asm("{ .reg .u64 t; cvta.to.shared.u64 t, %1; cvt.u32.u64 %0, t; }"
        : "=r"(a) : "l"(p));
    return a;
}

#define LDMX4(r, addr) \
    asm volatile("ldmatrix.sync.aligned.m8n8.x4.shared.b16 {%0,%1,%2,%3}, [%4];" \
        : "=r"((r)[0]), "=r"((r)[1]), "=r"((r)[2]), "=r"((r)[3]) \
        : "r"(addr))

__device__ __forceinline__ void mma_bf16(float* c, const uint32_t* a,
                                         const uint32_t* b) {
    asm volatile(
        "mma.sync.aligned.m16n8k16.row.col.f32.bf16.bf16.f32 "
        "{%0,%1,%2,%3}, {%4,%5,%6,%7}, {%8,%9}, {%0,%1,%2,%3};"
        : "+f"(c[0]), "+f"(c[1]), "+f"(c[2]), "+f"(c[3])
        : "r"(a[0]), "r"(a[1]), "r"(a[2]), "r"(a[3]), "r"(b[0]), "r"(b[1]));
}

#define CP_ASYNC16(dst, src) \
    asm volatile("cp.async.cg.shared.global [%0], [%1], 16;" \
        :: "r"(dst), "l"(src))
#define CP_COMMIT() asm volatile("cp.async.commit_group;" ::: "memory")
#define CP_WAIT1() asm volatile("cp.async.wait_group 1;" ::: "memory")
#define CP_WAIT0() asm volatile("cp.async.wait_group 0;" ::: "memory")

// Swizzled byte offset inside a 128x128 bf16 tile (256B rows, 16B chunks,
// chunk column XOR'd with row%8 -> conflict-free ldmatrix).
__device__ __forceinline__ uint32_t tswz(int row, int col2b) {
    return (uint32_t)(row * 256 + ((((col2b >> 3) ^ (row & 7)) << 4) |
                                   ((col2b & 7) * 2)));
}

// Order-preserving float <-> uint
__device__ __forceinline__ unsigned fford(float f) {
    unsigned u = __float_as_uint(f);
    return (u & 0x80000000u) ? ~u : (u | 0x80000000u);
}
__device__ __forceinline__ float fford_inv(unsigned u) {
    unsigned b = (u & 0x80000000u) ? (u & 0x7fffffffu) : ~u;
    return __uint_as_float(b);
}

// ---------------------------------------------------------------------------
// Prep: per code row v, csq[v] and bf16-hi conversion. One warp per row.
// ---------------------------------------------------------------------------
__global__ void prep_kernel(const float* __restrict__ cb) {
    int v = (blockIdx.x * blockDim.x + threadIdx.x) >> 5;
    int lane = threadIdx.x & 31;
    if (v >= VQ) return;
    const float4 x4 = *(const float4*)(cb + (size_t)v * DQ + lane * 4);
    float s = x4.x * x4.x + x4.y * x4.y + x4.z * x4.z + x4.w * x4.w;
#pragma unroll
    for (int off = 16; off; off >>= 1)
        s += __shfl_down_sync(0xffffffffu, s, off);
    if (lane == 0) g_csq[v] = s;
    __nv_bfloat162 p0 = __nv_bfloat162(__float2bfloat16(x4.x),
                                       __float2bfloat16(x4.y));
    __nv_bfloat162 p1 = __nv_bfloat162(__float2bfloat16(x4.z),
                                       __float2bfloat16(x4.w));
    *(__nv_bfloat162*)(g_ch + (size_t)v * DQ + lane * 4) = p0;
    *(__nv_bfloat162*)(g_ch + (size_t)v * DQ + lane * 4 + 2) = p1;
}

// ---------------------------------------------------------------------------
// Main: cheap bf16 GEMM screen -> candidate queue -> exact fp32 rescore ->
// codes + fused quantized gather.
// ---------------------------------------------------------------------------
__global__ void __launch_bounds__(256, 1)
vq_kernel(const float* __restrict__ latents, const float* __restrict__ cb,
          float* __restrict__ codes, float* __restrict__ quant) {
    extern __shared__ unsigned char sm[];
    const uint32_t smb = smem_u32(sm);
    const int tid = threadIdx.x;
    const int lane = tid & 31;
    const int wid = tid >> 5;
    const int warp_m = wid & 3;
    const int warp_n = wid >> 2;
    const int b = blockIdx.y;
    const int t0 = blockIdx.x * TILE_M;

    unsigned long long* res = (unsigned long long*)(sm + OFF_RES);
    unsigned* rowmin = (unsigned*)(sm + OFF_ROWMIN);
    unsigned* qn = (unsigned*)(sm + OFF_QN);
    float* csq_s = (float*)(sm + OFF_CSQ);
    float* Af = (float*)(sm + OFF_AF);
    unsigned* queue = (unsigned*)(sm + OFF_QUEUE);

    // Prefetch B chunk 0 immediately (overlaps with A conversion below)
    {
        const __nv_bfloat16* src = g_ch;
        for (int i = tid; i < 2048; i += 256) {
            int n = i >> 4, c = i & 15;
            CP_ASYNC16(smb + OFF_B + tswz(n, c * 8),
                       (const void*)(src + n * DQ + c * 8));
        }
        CP_COMMIT();
    }

    if (tid < 128) {
        res[tid] = ~0ull;
        rowmin[tid] = 0xFFFFFFFFu;
    }
    if (tid == 0) *qn = 0;
    for (int i = tid; i < VQ; i += 256) csq_s[i] = g_csq[i];

    // A: latents[b][d][t0+t] -> bf16-hi swizzled tile + fp32 copy
    {
        const float* xg = latents + (size_t)b * DQ * TQ + t0;
        for (int idx = tid; idx < DQ * TILE_M; idx += 256) {
            int d = idx >> 7;
            int t = idx & 127;     // coalesced over t
            float x = xg[(size_t)d * TQ + t];
            *(__nv_bfloat16*)(sm + OFF_AH + tswz(t, d)) = __float2bfloat16(x);
            Af[t * AF_STRIDE + d] = x;
        }
    }

    // Per-thread ldmatrix constants (layout validated in R5)
    const int arow_in16 = lane & 15;
    const int kca = lane >> 4;
    const int brow_in16 = (lane & 7) | ((lane >> 4) << 3);
    const int kcb = (lane >> 3) & 1;

    int axr[2];
    uint32_t abase[2];
#pragma unroll
    for (int mi = 0; mi < 2; mi++) {
        int row = warp_m * 32 + mi * 16 + arow_in16;
        axr[mi] = row & 7;
        abase[mi] = (uint32_t)(row * 256);
    }
    int bxr[4];
    uint32_t bbase[4];
#pragma unroll
    for (int n4 = 0; n4 < 4; n4++) {
        int row = warp_n * 64 + n4 * 16 + brow_in16;
        bxr[n4] = row & 7;
        bbase[n4] = (uint32_t)(row * 256);
    }

    for (int vc = 0; vc < NCHUNK; vc++) {
        const int v0 = vc * TILE_N;
        const int buf = vc & 1;

        // Prefetch next B chunk into the other buffer
        if (vc < NCHUNK - 1) {
            const __nv_bfloat16* src = g_ch + (size_t)(v0 + TILE_N) * DQ;
            uint32_t dbase = smb + OFF_B + (buf ^ 1) * BTILE;
            for (int i = tid; i < 2048; i += 256) {
                int n = i >> 4, c = i & 15;
                CP_ASYNC16(dbase + tswz(n, c * 8),
                           (const void*)(src + n * DQ + c * 8));
            }
            CP_COMMIT();
            CP_WAIT1();
        } else {
            CP_WAIT0();
        }
        __syncthreads();   // buf[vc] visible; A tile ready (vc==0)

        float acc[2][8][4];
#pragma unroll
        for (int mi = 0; mi < 2; mi++)
#pragma unroll
            for (int ni = 0; ni < 8; ni++)
#pragma unroll
                for (int q = 0; q < 4; q++) acc[mi][ni][q] = 0.f;

        const uint32_t bsm = smb + OFF_B + buf * BTILE;
#pragma unroll
        for (int ks = 0; ks < 8; ks++) {
            uint32_t aH[2][4];
#pragma unroll
            for (int mi = 0; mi < 2; mi++) {
                uint32_t co = (uint32_t)((((ks << 1) | kca) ^ axr[mi]) << 4);
                LDMX4(aH[mi], smb + OFF_AH + abase[mi] + co);
            }
            uint32_t bH[8][2];
#pragma unroll
            for (int n4 = 0; n4 < 4; n4++) {
                uint32_t co = (uint32_t)((((ks << 1) | kcb) ^ bxr[n4]) << 4);
                uint32_t r[4];
                LDMX4(r, bsm + bbase[n4] + co);
                bH[n4 * 2][0] = r[0]; bH[n4 * 2][1] = r[1];
                bH[n4 * 2 + 1][0] = r[2]; bH[n4 * 2 + 1][1] = r[3];
            }
#pragma unroll
            for (int mi = 0; mi < 2; mi++)
#pragma unroll
                for (int ni = 0; ni < 8; ni++)
                    mma_bf16(acc[mi][ni], aH[mi], bH[ni]);
        }

        // Pass 1: per-row cheap min -> smem running min (order-uint atomicMin)
        float rm[4];
#pragma unroll
        for (int j = 0; j < 4; j++) rm[j] = 3.4e38f;
#pragma unroll
        for (int ni = 0; ni < 8; ni++) {
            int col0 = v0 + warp_n * 64 + ni * 8 + (lane & 3) * 2;
            float cs0 = csq_s[col0], cs1 = csq_s[col0 + 1];
#pragma unroll
            for (int mi = 0; mi < 2; mi++) {
                const float* c = acc[mi][ni];
                float s0 = fmaf(-2.f, c[0], cs0);
                float s1 = fmaf(-2.f, c[1], cs1);
                float s2 = fmaf(-2.f, c[2], cs0);
                float s3 = fmaf(-2.f, c[3], cs1);
                float m01 = fminf(s0, s1), m23 = fminf(s2, s3);
                if (m01 < rm[mi * 2]) rm[mi * 2] = m01;
                if (m23 < rm[mi * 2 + 1]) rm[mi * 2 + 1] = m23;
            }
        }
#pragma unroll
        for (int j = 0; j < 4; j++) {
            int row = warp_m * 32 + (j >> 1) * 16 + (j & 1) * 8 + (lane >> 2);
            atomicMin(&rowmin[row], fford(rm[j]));
        }
        __syncthreads();

        // Pass 2: insert candidates within MARGIN of running row min
#pragma unroll
        for (int mi = 0; mi < 2; mi++) {
            int rA = warp_m * 32 + mi * 16 + (lane >> 2);
            float thA = fford_inv(rowmin[rA]) + MARGIN;
            float thB = fford_inv(rowmin[rA + 8]) + MARGIN;
#pragma unroll
            for (int ni = 0; ni < 8; ni++) {
                int col0 = v0 + warp_n * 64 + ni * 8 + (lane & 3) * 2;
                float cs0 = csq_s[col0], cs1 = csq_s[col0 + 1];
                const float* c = acc[mi][ni];
                float s0 = fmaf(-2.f, c[0], cs0);
                float s1 = fmaf(-2.f, c[1], cs1);
                float s2 = fmaf(-2.f, c[2], cs0);
                float s3 = fmaf(-2.f, c[3], cs1);
                if (s0 <= thA) {
                    unsigned k = atomicAdd(qn, 1u);
                    if (k < QCAP) queue[k] = ((unsigned)rA << 10) | col0;
                }
                if (s1 <= thA) {
                    unsigned k = atomicAdd(qn, 1u);
                    if (k < QCAP) queue[k] = ((unsigned)rA << 10) | (col0 + 1);
                }
                if (s2 <= thB) {
                    unsigned k = atomicAdd(qn, 1u);
                    if (k < QCAP) queue[k] = ((unsigned)(rA + 8) << 10) | col0;
                }
                if (s3 <= thB) {
                    unsigned k = atomicAdd(qn, 1u);
                    if (k < QCAP) queue[k] = ((unsigned)(rA + 8) << 10) | (col0 + 1);
                }
            }
        }
        // loop-top syncthreads separates pass-2 from next chunk's use
    }
    __syncthreads();

    // Exact fp32 rescore of candidates: one warp per queue entry
    {
        unsigned n = *qn;
        if (n > QCAP) n = QCAP;
        for (unsigned e = wid; e < n; e += 8) {
            unsigned ent = queue[e];
            int r = ent >> 10;
            int v = ent & 1023;
            const float4 xa = *(const float4*)(Af + r * AF_STRIDE + lane * 4);
            const float4 ca = *(const float4*)(cb + (size_t)v * DQ + lane * 4);
            float s = xa.x * ca.x + xa.y * ca.y + xa.z * ca.z + xa.w * ca.w;
#pragma unroll
            for (int off = 16; off; off >>= 1)
                s += __shfl_down_sync(0xffffffffu, s, off);
            if (lane == 0) {
                float score = fmaf(-2.f, s, csq_s[v]);
                unsigned long long pk =
                    ((unsigned long long)fford(score) << 32) | (unsigned)v;
                atomicMin(&res[r], pk);
            }
        }
    }
    __syncthreads();

    // Write codes (as float) and fused quantized gather
    if (tid < 128)
        codes[(size_t)b * TQ + t0 + tid] = (float)(unsigned)(res[tid] & 1023u);

    {
        int t = tid & 127;
        int dh = tid >> 7;                 // 0 or 1: d-halves
        int v = (int)(res[t] & 1023u);
        const float* crow = cb + (size_t)v * DQ + dh * 64;
        float* q = quant + (size_t)b * DQ * TQ + (size_t)(dh * 64) * TQ + t0 + t;
#pragma unroll
        for (int i = 0; i < 16; i++) {
            float4 c4 = *(const float4*)(crow + i * 4);
            q[(i * 4 + 0) * TQ] = c4.x;
            q[(i * 4 + 1) * TQ] = c4.y;
            q[(i * 4 + 2) * TQ] = c4.z;
            q[(i * 4 + 3) * TQ] = c4.w;
        }
    }
}

// ---------------------------------------------------------------------------
extern "C" void kernel_launch(void* const* d_in, const int* in_sizes, int n_in,
                              void* d_out, int out_size) {
    const float* latents = (const float*)d_in[0];   // (B, D, T) fp32
    const float* codebook = (const float*)d_in[1];  // (V, D)    fp32

    float* codes = (float*)d_out;             // B*T floats
    float* quant = (float*)d_out + BQ * TQ;   // B*D*T floats

    cudaFuncSetAttribute(vq_kernel,
                         cudaFuncAttributeMaxDynamicSharedMemorySize,
                         SMEM_TOTAL);

    prep_kernel<<<(VQ * 32) / 256, 256>>>(codebook);

    dim3 grid(TQ / TILE_M, BQ);   // (32, 16) = 512 blocks
    vq_kernel<<<grid, 256, SMEM_TOTAL>>>(latents, codebook, codes, quant);
}

// round 7
// speedup vs baseline: 4.3663x; 1.3736x over previous
#include <cuda_runtime.h>
#include <cuda_bf16.h>
#include <cstdint>

// Problem constants
#define BQ 16
#define DQ 128
#define TQ 4096
#define VQ 1024

#define TILE_M 128
#define TILE_N 128
#define NCHUNK 8
#define MARGIN 3.0f
#define QCAP 8192
#define NTHREADS 512

// Dynamic SMEM layout (bytes)
#define OFF_RES    0          // 128 x u64 packed (score,idx)
#define OFF_ROWMIN 1024       // 128 x u32 (order-uint running cheap min)
#define OFF_QN     1536       // queue counter
#define OFF_CSQ    2048       // 1024 floats
#define OFF_AF     6144       // fp32 A [128][AF_STRIDE]
#define AF_STRIDE  132
#define OFF_AH     73728      // bf16 A tile 32KB (swizzled)
#define OFF_B      106496     // bf16 B tiles, 2 x 32KB (double buffer)
#define BTILE      32768
#define OFF_QUEUE  172032     // QCAP x u32
#define SMEM_TOTAL 204800

__device__ float g_csq[VQ];
__device__ __nv_bfloat16 g_ch[VQ * DQ];

// ---------------------------------------------------------------------------
__device__ __forceinline__ uint32_t smem_u32(const void* p) {
    uint32_t a;
    asm("{ .reg .u64 t; cvta.to.shared.u64 t, %1; cvt.u32.u64 %0, t; }"
        : "=r"(a) : "l"(p));
    return a;
}

#define LDMX4(r, addr) \
    asm volatile("ldmatrix.sync.aligned.m8n8.x4.shared.b16 {%0,%1,%2,%3}, [%4];" \
        : "=r"((r)[0]), "=r"((r)[1]), "=r"((r)[2]), "=r"((r)[3]) \
        : "r"(addr))

__device__ __forceinline__ void mma_bf16(float* c, const uint32_t* a,
                                         const uint32_t* b) {
    asm volatile(
        "mma.sync.aligned.m16n8k16.row.col.f32.bf16.bf16.f32 "
        "{%0,%1,%2,%3}, {%4,%5,%6,%7}, {%8,%9}, {%0,%1,%2,%3};"
        : "+f"(c[0]), "+f"(c[1]), "+f"(c[2]), "+f"(c[3])
        : "r"(a[0]), "r"(a[1]), "r"(a[2]), "r"(a[3]), "r"(b[0]), "r"(b[1]));
}

#define CP_ASYNC16(dst, src) \
    asm volatile("cp.async.cg.shared.global [%0], [%1], 16;" \
        :: "r"(dst), "l"(src))
#define CP_COMMIT() asm volatile("cp.async.commit_group;" ::: "memory")
#define CP_WAIT1() asm volatile("cp.async.wait_group 1;" ::: "memory")
#define CP_WAIT0() asm volatile("cp.async.wait_group 0;" ::: "memory")

// Swizzled byte offset inside a 128x128 bf16 tile (256B rows, 16B chunks,
// chunk column XOR'd with row%8 -> conflict-free ldmatrix).
__device__ __forceinline__ uint32_t tswz(int row, int col2b) {
    return (uint32_t)(row * 256 + ((((col2b >> 3) ^ (row & 7)) << 4) |
                                   ((col2b & 7) * 2)));
}

// Order-preserving float <-> uint
__device__ __forceinline__ unsigned fford(float f) {
    unsigned u = __float_as_uint(f);
    return (u & 0x80000000u) ? ~u : (u | 0x80000000u);
}
__device__ __forceinline__ float fford_inv(unsigned u) {
    unsigned b = (u & 0x80000000u) ? (u & 0x7fffffffu) : ~u;
    return __uint_as_float(b);
}

// ---------------------------------------------------------------------------
// Prep: per code row v, csq[v] and bf16-hi conversion. One warp per row.
// ---------------------------------------------------------------------------
__global__ void prep_kernel(const float* __restrict__ cb) {
    int v = (blockIdx.x * blockDim.x + threadIdx.x) >> 5;
    int lane = threadIdx.x & 31;
    if (v >= VQ) return;
    const float4 x4 = *(const float4*)(cb + (size_t)v * DQ + lane * 4);
    float s = x4.x * x4.x + x4.y * x4.y + x4.z * x4.z + x4.w * x4.w;
#pragma unroll
    for (int off = 16; off; off >>= 1)
        s += __shfl_down_sync(0xffffffffu, s, off);
    if (lane == 0) g_csq[v] = s;
    __nv_bfloat162 p0 = __nv_bfloat162(__float2bfloat16(x4.x),
                                       __float2bfloat16(x4.y));
    __nv_bfloat162 p1 = __nv_bfloat162(__float2bfloat16(x4.z),
                                       __float2bfloat16(x4.w));
    *(__nv_bfloat162*)(g_ch + (size_t)v * DQ + lane * 4) = p0;
    *(__nv_bfloat162*)(g_ch + (size_t)v * DQ + lane * 4 + 2) = p1;
}

// ---------------------------------------------------------------------------
// Main: cheap bf16 GEMM screen -> candidate queue -> exact fp32 rescore ->
// codes + fused quantized gather.  512 threads, 16 warps in a 4x4 grid,
// warp tile 32x32, CTA tile 128x128x128, V in 8 chunks.
// ---------------------------------------------------------------------------
__global__ void __launch_bounds__(NTHREADS, 1)
vq_kernel(const float* __restrict__ latents, const float* __restrict__ cb,
          float* __restrict__ codes, float* __restrict__ quant) {
    extern __shared__ unsigned char sm[];
    const uint32_t smb = smem_u32(sm);
    const int tid = threadIdx.x;
    const int lane = tid & 31;
    const int wid = tid >> 5;
    const int warp_m = wid & 3;    // 4 m-tiles of 32 rows
    const int warp_n = wid >> 2;   // 4 n-tiles of 32 cols
    const int b = blockIdx.y;
    const int t0 = blockIdx.x * TILE_M;

    unsigned long long* res = (unsigned long long*)(sm + OFF_RES);
    unsigned* rowmin = (unsigned*)(sm + OFF_ROWMIN);
    unsigned* qn = (unsigned*)(sm + OFF_QN);
    float* csq_s = (float*)(sm + OFF_CSQ);
    float* Af = (float*)(sm + OFF_AF);
    unsigned* queue = (unsigned*)(sm + OFF_QUEUE);

    // Prefetch B chunk 0 immediately (overlaps with A conversion below)
    {
        const __nv_bfloat16* src = g_ch;
        for (int i = tid; i < 2048; i += NTHREADS) {
            int n = i >> 4, c = i & 15;
            CP_ASYNC16(smb + OFF_B + tswz(n, c * 8),
                       (const void*)(src + n * DQ + c * 8));
        }
        CP_COMMIT();
    }

    if (tid < 128) {
        res[tid] = ~0ull;
        rowmin[tid] = 0xFFFFFFFFu;
    }
    if (tid == 0) *qn = 0;
    for (int i = tid; i < VQ; i += NTHREADS) csq_s[i] = g_csq[i];

    // A: latents[b][d][t0+t] -> bf16-hi swizzled tile + fp32 copy
    {
        const float* xg = latents + (size_t)b * DQ * TQ + t0;
        for (int idx = tid; idx < DQ * TILE_M; idx += NTHREADS) {
            int d = idx >> 7;
            int t = idx & 127;     // coalesced over t
            float x = xg[(size_t)d * TQ + t];
            *(__nv_bfloat16*)(sm + OFF_AH + tswz(t, d)) = __float2bfloat16(x);
            Af[t * AF_STRIDE + d] = x;
        }
    }

    // Per-thread ldmatrix constants (layout validated in R5/R6)
    const int arow_in16 = lane & 15;
    const int kca = lane >> 4;
    const int brow_in16 = (lane & 7) | ((lane >> 4) << 3);
    const int kcb = (lane >> 3) & 1;

    int axr[2];
    uint32_t abase[2];
#pragma unroll
    for (int mi = 0; mi < 2; mi++) {
        int row = warp_m * 32 + mi * 16 + arow_in16;
        axr[mi] = row & 7;
        abase[mi] = (uint32_t)(row * 256);
    }
    int bxr[2];
    uint32_t bbase[2];
#pragma unroll
    for (int n4 = 0; n4 < 2; n4++) {
        int row = warp_n * 32 + n4 * 16 + brow_in16;
        bxr[n4] = row & 7;
        bbase[n4] = (uint32_t)(row * 256);
    }

    for (int vc = 0; vc < NCHUNK; vc++) {
        const int v0 = vc * TILE_N;
        const int buf = vc & 1;

        // Prefetch next B chunk into the other buffer
        if (vc < NCHUNK - 1) {
            const __nv_bfloat16* src = g_ch + (size_t)(v0 + TILE_N) * DQ;
            uint32_t dbase = smb + OFF_B + (buf ^ 1) * BTILE;
            for (int i = tid; i < 2048; i += NTHREADS) {
                int n = i >> 4, c = i & 15;
                CP_ASYNC16(dbase + tswz(n, c * 8),
                           (const void*)(src + n * DQ + c * 8));
            }
            CP_COMMIT();
            CP_WAIT1();
        } else {
            CP_WAIT0();
        }
        __syncthreads();   // buf[vc] visible; A tile ready (vc==0)

        float acc[2][4][4];
#pragma unroll
        for (int mi = 0; mi < 2; mi++)
#pragma unroll
            for (int ni = 0; ni < 4; ni++)
#pragma unroll
                for (int q = 0; q < 4; q++) acc[mi][ni][q] = 0.f;

        const uint32_t bsm = smb + OFF_B + buf * BTILE;
#pragma unroll
        for (int ks = 0; ks < 8; ks++) {
            uint32_t aH[2][4];
#pragma unroll
            for (int mi = 0; mi < 2; mi++) {
                uint32_t co = (uint32_t)((((ks << 1) | kca) ^ axr[mi]) << 4);
                LDMX4(aH[mi], smb + OFF_AH + abase[mi] + co);
            }
            uint32_t bH[4][2];
#pragma unroll
            for (int n4 = 0; n4 < 2; n4++) {
                uint32_t co = (uint32_t)((((ks << 1) | kcb) ^ bxr[n4]) << 4);
                uint32_t r[4];
                LDMX4(r, bsm + bbase[n4] + co);
                bH[n4 * 2][0] = r[0]; bH[n4 * 2][1] = r[1];
                bH[n4 * 2 + 1][0] = r[2]; bH[n4 * 2 + 1][1] = r[3];
            }
#pragma unroll
            for (int mi = 0; mi < 2; mi++)
#pragma unroll
                for (int ni = 0; ni < 4; ni++)
                    mma_bf16(acc[mi][ni], aH[mi], bH[ni]);
        }

        // Convert acc -> cheap scores in place, track per-thread row mins
        float rm[4];
#pragma unroll
        for (int j = 0; j < 4; j++) rm[j] = 3.4e38f;
#pragma unroll
        for (int ni = 0; ni < 4; ni++) {
            int col0 = v0 + warp_n * 32 + ni * 8 + (lane & 3) * 2;
            float cs0 = csq_s[col0], cs1 = csq_s[col0 + 1];
#pragma unroll
            for (int mi = 0; mi < 2; mi++) {
                float* c = acc[mi][ni];
                c[0] = fmaf(-2.f, c[0], cs0);
                c[1] = fmaf(-2.f, c[1], cs1);
                c[2] = fmaf(-2.f, c[2], cs0);
                c[3] = fmaf(-2.f, c[3], cs1);
                float m01 = fminf(c[0], c[1]), m23 = fminf(c[2], c[3]);
                if (m01 < rm[mi * 2]) rm[mi * 2] = m01;
                if (m23 < rm[mi * 2 + 1]) rm[mi * 2 + 1] = m23;
            }
        }
#pragma unroll
        for (int j = 0; j < 4; j++) {
            int row = warp_m * 32 + (j >> 1) * 16 + (j & 1) * 8 + (lane >> 2);
            atomicMin(&rowmin[row], fford(rm[j]));
        }
        __syncthreads();

        // Insert candidates within MARGIN of running row min
#pragma unroll
        for (int mi = 0; mi < 2; mi++) {
            int rA = warp_m * 32 + mi * 16 + (lane >> 2);
            float thA = fford_inv(rowmin[rA]) + MARGIN;
            float thB = fford_inv(rowmin[rA + 8]) + MARGIN;
#pragma unroll
            for (int ni = 0; ni < 4; ni++) {
                int col0 = v0 + warp_n * 32 + ni * 8 + (lane & 3) * 2;
                const float* c = acc[mi][ni];
                if (c[0] <= thA) {
                    unsigned k = atomicAdd(qn, 1u);
                    if (k < QCAP) queue[k] = ((unsigned)rA << 10) | col0;
                }
                if (c[1] <= thA) {
                    unsigned k = atomicAdd(qn, 1u);
                    if (k < QCAP) queue[k] = ((unsigned)rA << 10) | (col0 + 1);
                }
                if (c[2] <= thB) {
                    unsigned k = atomicAdd(qn, 1u);
                    if (k < QCAP) queue[k] = ((unsigned)(rA + 8) << 10) | col0;
                }
                if (c[3] <= thB) {
                    unsigned k = atomicAdd(qn, 1u);
                    if (k < QCAP) queue[k] = ((unsigned)(rA + 8) << 10) | (col0 + 1);
                }
            }
        }
        // loop-top syncthreads separates pass-2 from next chunk's use
    }
    __syncthreads();

    // Exact fp32 rescore of candidates: one warp per queue entry
    {
        unsigned n = *qn;
        if (n > QCAP) n = QCAP;
        for (unsigned e = wid; e < n; e += 16) {
            unsigned ent = queue[e];
            int r = ent >> 10;
            int v = ent & 1023;
            const float4 xa = *(const float4*)(Af + r * AF_STRIDE + lane * 4);
            const float4 ca = *(const float4*)(cb + (size_t)v * DQ + lane * 4);
            float s = xa.x * ca.x + xa.y * ca.y + xa.z * ca.z + xa.w * ca.w;
#pragma unroll
            for (int off = 16; off; off >>= 1)
                s += __shfl_down_sync(0xffffffffu, s, off);
            if (lane == 0) {
                float score = fmaf(-2.f, s, csq_s[v]);
                unsigned long long pk =
                    ((unsigned long long)fford(score) << 32) | (unsigned)v;
                atomicMin(&res[r], pk);
            }
        }
    }
    __syncthreads();

    // Write codes (as float) and fused quantized gather
    if (tid < 128)
        codes[(size_t)b * TQ + t0 + tid] = (float)(unsigned)(res[tid] & 1023u);

    {
        int t = tid & 127;
        int dh = tid >> 7;                 // 0..3: d-quarters
        int v = (int)(res[t] & 1023u);
        const float* crow = cb + (size_t)v * DQ + dh * 32;
        float* q = quant + (size_t)b * DQ * TQ + (size_t)(dh * 32) * TQ + t0 + t;
#pragma unroll
        for (int i = 0; i < 8; i++) {
            float4 c4 = *(const float4*)(crow + i * 4);
            q[(i * 4 + 0) * TQ] = c4.x;
            q[(i * 4 + 1) * TQ] = c4.y;
            q[(i * 4 + 2) * TQ] = c4.z;
            q[(i * 4 + 3) * TQ] = c4.w;
        }
    }
}

// ---------------------------------------------------------------------------
extern "C" void kernel_launch(void* const* d_in, const int* in_sizes, int n_in,
                              void* d_out, int out_size) {
    const float* latents = (const float*)d_in[0];   // (B, D, T) fp32
    const float* codebook = (const float*)d_in[1];  // (V, D)    fp32

    float* codes = (float*)d_out;             // B*T floats
    float* quant = (float*)d_out + BQ * TQ;   // B*D*T floats

    cudaFuncSetAttribute(vq_kernel,
                         cudaFuncAttributeMaxDynamicSharedMemorySize,
                         SMEM_TOTAL);

    prep_kernel<<<(VQ * 32) / 256, 256>>>(codebook);

    dim3 grid(TQ / TILE_M, BQ);   // (32, 16) = 512 blocks
    vq_kernel<<<grid, NTHREADS, SMEM_TOTAL>>>(latents, codebook, codes, quant);
}